// round 16
// baseline (speedup 1.0000x reference)
#include <cuda_runtime.h>
#include <cuda_bf16.h>

// MaskFiller: out[b, keep_ids[b,k], :] = inputs[b,k,:]
//             out[b, mask_ids[b,m], :] = mask_embedding[:]
// B=8, K=4096, M=4096, L=8192, D=512 (f32). Pure data movement; HBM bound.
//
// R15: gather v2. Evidence: HBM traffic/replay ~143MB = writes + ~15MB
// reads (input is already L2-resident), DRAM idle 38% -> the binding term
// is scattered-write DRAM efficiency (~4.4TB/s on the 128MB write stream).
// R10's gather regressed at occ 53% (U=8, 48 regs) -- confounded. This is
// gather at the proven-good geometry: U=4, 128 threads, occ-16, branchless
// pointer-select so every lane issues one unconditional load (mask rows
// read the L1-resident embedding). Writes become perfectly sequential.
//
// Inputs (metadata order):
//   d_in[0] inputs            float32 [B, K, D]
//   d_in[1] mask_position_ids int32   [B, M]
//   d_in[2] keep_position_ids int32   [B, K]
//   d_in[3] mask_embedding    float32 [D]
//   d_in[4] axis              (unused; always -2)

#define B_ 8
#define K_ 4096
#define M_ 4096
#define L_ (K_ + M_)
#define D_ 512
#define VPR 128          // float4 per row (D/4)
#define U_  4            // output rows per CTA in the gather kernel

// Inverse map: g_inv[b*L + l] = input row j (keep slot) or -1 (mask slot).
// 256 KB static scratch, fully rewritten every launch -> deterministic.
__device__ int g_inv[B_ * L_];

__global__ __launch_bounds__(256)
void build_inv_kernel(const int* __restrict__ mask_ids,
                      const int* __restrict__ keep_ids)
{
    const int t = blockIdx.x * 256 + threadIdx.x;   // 0 .. B*L-1
    const int b = t >> 13;                          // t / L_
    const int j = t & (L_ - 1);                     // t % L_
    if (j < K_) {
        const int pos = __ldg(&keep_ids[b * K_ + j]);
        g_inv[b * L_ + pos] = j;
    } else {
        const int pos = __ldg(&mask_ids[b * M_ + (j - K_)]);
        g_inv[b * L_ + pos] = -1;
    }
}

__global__ __launch_bounds__(128, 16)
void gather_kernel(const float4* __restrict__ inputs,
                   const float4* __restrict__ mask_emb,
                   float4*       __restrict__ out)
{
    // CTA writes U_ consecutive output rows l0..l0+3 of batch b.
    const int t0  = blockIdx.x * U_;
    const int b   = t0 >> 13;            // t0 / L_
    const int l0  = t0 & (L_ - 1);       // t0 % L_
    const int tid = threadIdx.x;         // 0..127, one float4 column

    const float4* __restrict__ in_b = inputs + (size_t)b * K_ * VPR;

    // Branchless source selection: keep rows gather from input (mostly
    // L2-hit), mask rows read the L1-resident embedding. One unconditional
    // load per (u, lane); 4-deep front-batched MLP.
    const float4* p[U_];
    #pragma unroll
    for (int u = 0; u < U_; ++u) {
        const int s = __ldg(&g_inv[b * L_ + l0 + u]);   // uniform broadcast
        p[u] = (s >= 0) ? (in_b + (size_t)s * VPR + tid) : (mask_emb + tid);
    }

    float4 v[U_];
    #pragma unroll
    for (int u = 0; u < U_; ++u)
        v[u] = __ldg(p[u]);

    // Perfectly sequential streaming writes: CTA covers 8 KB contiguous,
    // consecutive CTAs tile the output linearly.
    float4* __restrict__ dst = out + ((size_t)b * L_ + l0) * VPR + tid;
    #pragma unroll
    for (int u = 0; u < U_; ++u)
        __stcs(dst + u * VPR, v[u]);
}

extern "C" void kernel_launch(void* const* d_in, const int* in_sizes, int n_in,
                              void* d_out, int out_size)
{
    const float4* inputs   = (const float4*)d_in[0];
    const int*    mask_ids = (const int*)   d_in[1];
    const int*    keep_ids = (const int*)   d_in[2];
    const float4* mask_emb = (const float4*)d_in[3];
    float4*       out      = (float4*)      d_out;

    (void)in_sizes; (void)n_in; (void)out_size;

    // Phase 1: build inverse permutation (L2-resident, ~1-2us).
    build_inv_kernel<<<(B_ * L_) / 256, 256>>>(mask_ids, keep_ids);

    // Phase 2: gather with linear output writes. 16384 CTAs x 128 threads.
    gather_kernel<<<(B_ * L_) / U_, 128>>>(inputs, mask_emb, out);
}

// round 17
// speedup vs baseline: 1.0769x; 1.0769x over previous
#include <cuda_runtime.h>
#include <cuda_bf16.h>

// MaskFiller: out[b, keep_ids[b,k], :] = inputs[b,k,:]
//             out[b, mask_ids[b,m], :] = mask_embedding[:]
// B=8, K=4096, M=4096, L=8192, D=512 (f32). Pure scatter-copy.
//
// R16: LTS-roofline model. Scatter (R4, 28.0us) and sequential-write gather
// (R15, 29.6us) hit the same kernel floor -> write pattern irrelevant; the
// bound is compulsory L2-crossing traffic: 192MB / 28us = 6.86 TB/s ~= the
// ~6300 B/cyc LTS chip cap. Remaining lever: the task order phase-alternates
// between keep waves (read+write) and mask waves (write-only). This round
// interleaves keep/mask CTAs (even/odd blockIdx) so every resident wave
// presents a stationary ~2:1 write:read mix to LTS/DRAM instead of
// alternating regimes with turnaround at phase boundaries.
//
// Inputs (metadata order):
//   d_in[0] inputs            float32 [B, K, D]
//   d_in[1] mask_position_ids int32   [B, M]
//   d_in[2] keep_position_ids int32   [B, K]
//   d_in[3] mask_embedding    float32 [D]
//   d_in[4] axis              (unused; always -2)

#define B_ 8
#define K_ 4096
#define M_ 4096
#define L_ (K_ + M_)
#define D_ 512
#define VPR 128          // float4 per row (D/4)
#define U_  4            // rows per CTA
#define CTAS_PER_BATCH (L_ / U_)   // 2048: 1024 keep + 1024 mask, interleaved

__global__ __launch_bounds__(128, 16)
void maskfiller_kernel(const float4* __restrict__ inputs,
                       const int*    __restrict__ mask_ids,
                       const int*    __restrict__ keep_ids,
                       const float4* __restrict__ mask_emb,
                       float4*       __restrict__ out)
{
    // Interleaved task map: within each batch, even CTAs take keep tasks,
    // odd CTAs take mask tasks, so each scheduling wave carries a uniform
    // write:read mix (keep = read 512B/thread-row + write; mask = write-only).
    const int c   = blockIdx.x;
    const int b   = c >> 11;             // c / CTAS_PER_BATCH (2048)
    const int r   = c & (CTAS_PER_BATCH - 1);
    const int tid = threadIdx.x;         // 0..127, one float4 column

    float4* __restrict__ out_b = out + (size_t)b * L_ * VPR;

    if ((r & 1) == 0) {
        // keep path: tasks j0 = (r/2)*U_ .. +U_-1, copy input rows to
        // scattered output rows.
        const int j0 = (r >> 1) * U_;

        int rows[U_];
        #pragma unroll
        for (int u = 0; u < U_; ++u)
            rows[u] = __ldg(&keep_ids[b * K_ + j0 + u]);

        const float4* __restrict__ src =
            inputs + ((size_t)b * K_ + j0) * VPR + tid;
        float4 v[U_];
        #pragma unroll
        for (int u = 0; u < U_; ++u)
            v[u] = __ldcs(src + u * VPR);          // 4 independent loads

        #pragma unroll
        for (int u = 0; u < U_; ++u)
            __stcs(&out_b[(size_t)rows[u] * VPR + tid], v[u]);
    } else {
        // mask path: broadcast embedding into U_ scattered output rows.
        const int m0 = (r >> 1) * U_;

        const float4 v = __ldg(&mask_emb[tid]);    // L2/L1 resident
        int rows[U_];
        #pragma unroll
        for (int u = 0; u < U_; ++u)
            rows[u] = __ldg(&mask_ids[b * M_ + m0 + u]);

        #pragma unroll
        for (int u = 0; u < U_; ++u)
            __stcs(&out_b[(size_t)rows[u] * VPR + tid], v);
    }
}

extern "C" void kernel_launch(void* const* d_in, const int* in_sizes, int n_in,
                              void* d_out, int out_size)
{
    const float4* inputs   = (const float4*)d_in[0];
    const int*    mask_ids = (const int*)   d_in[1];
    const int*    keep_ids = (const int*)   d_in[2];
    const float4* mask_emb = (const float4*)d_in[3];
    float4*       out      = (float4*)      d_out;

    (void)in_sizes; (void)n_in; (void)out_size;

    // 16384 CTAs, 128 threads, 4 rows per CTA, keep/mask interleaved.
    maskfiller_kernel<<<B_ * CTAS_PER_BATCH, 128>>>(inputs, mask_ids, keep_ids,
                                                    mask_emb, out);
}